// round 16
// baseline (speedup 1.0000x reference)
#include <cuda_runtime.h>
#include <cuda_fp16.h>
#include <cstdint>

#define NT     49
#define DIMC   256
#define NH     8
#define HD     32
#define QSCALE 0.17677669529663687f   // 32^-0.5
#define MAXB   4096
#define MAXW   64

// ------------------------- global scratch ---------------------------------
__device__ __half g_Xh [(size_t)MAXB * NT * DIMC];        // fp16 x
__device__ __half g_QKV[(size_t)MAXB * NT * 3 * DIMC];    // fp16 qkv activations
__device__ __half g_Oh [(size_t)MAXB * NT * DIMC];        // fp16 attention out
__device__ __half g_Wq [3 * DIMC * DIMC];                 // fp16 qkv_w
__device__ __half g_Wp [DIMC * DIMC];                     // fp16 proj_w
__device__ float  g_BM [(size_t)MAXW * NH * NT * 56];     // bias+mask, pad=-1e30

// ---------------------------------------------------------------------------
__device__ __forceinline__ void cpa16(void* smem_dst, const void* gsrc) {
    unsigned d = (unsigned)__cvta_generic_to_shared(smem_dst);
    asm volatile("cp.async.cg.shared.global [%0], [%1], 16;" :: "r"(d), "l"(gsrc));
}

__device__ __forceinline__ void mma16(float* c,
                                      uint32_t a0, uint32_t a1, uint32_t a2, uint32_t a3,
                                      uint32_t b0, uint32_t b1) {
    asm volatile(
        "mma.sync.aligned.m16n8k16.row.col.f32.f16.f16.f32 "
        "{%0,%1,%2,%3}, {%4,%5,%6,%7}, {%8,%9}, {%0,%1,%2,%3};"
        : "+f"(c[0]), "+f"(c[1]), "+f"(c[2]), "+f"(c[3])
        : "r"(a0), "r"(a1), "r"(a2), "r"(a3), "r"(b0), "r"(b1));
}

__device__ __forceinline__ void ldsm4(uint32_t& r0, uint32_t& r1,
                                      uint32_t& r2, uint32_t& r3, uint32_t addr) {
    asm volatile("ldmatrix.sync.aligned.m8n8.x4.shared.b16 {%0,%1,%2,%3}, [%4];"
                 : "=r"(r0), "=r"(r1), "=r"(r2), "=r"(r3) : "r"(addr));
}

__device__ __forceinline__ void ldsm4t(uint32_t& r0, uint32_t& r1,
                                       uint32_t& r2, uint32_t& r3, uint32_t addr) {
    asm volatile("ldmatrix.sync.aligned.m8n8.x4.trans.shared.b16 {%0,%1,%2,%3}, [%4];"
                 : "=r"(r0), "=r"(r1), "=r"(r2), "=r"(r3) : "r"(addr));
}

// ===========================================================================
// prep kernels: fp32 -> fp16 conversion + bias/mask table
// ===========================================================================
__global__ void convX(const float4* __restrict__ src, __half2* __restrict__ dst) {
    size_t i = (size_t)blockIdx.x * 256 + threadIdx.x;
    float4 v = src[i];
    dst[2 * i]     = __floats2half2_rn(v.x, v.y);
    dst[2 * i + 1] = __floats2half2_rn(v.z, v.w);
}

__global__ void convW(const float4* __restrict__ qw, const float4* __restrict__ pw,
                      __half2* __restrict__ qwt, __half2* __restrict__ pwt) {
    int i = blockIdx.x * 256 + threadIdx.x;          // 65536 threads
    if (i < 49152) {
        float4 v = qw[i];
        qwt[2 * i]     = __floats2half2_rn(v.x, v.y);
        qwt[2 * i + 1] = __floats2half2_rn(v.z, v.w);
    } else {
        int j = i - 49152;
        float4 v = pw[j];
        pwt[2 * j]     = __floats2half2_rn(v.x, v.y);
        pwt[2 * j + 1] = __floats2half2_rn(v.z, v.w);
    }
}

__global__ void prepBM(const float* __restrict__ mask,
                       const float* __restrict__ btab) {
    const int h = blockIdx.x, w = blockIdx.y;
    float* dst = g_BM + ((size_t)(w * NH + h) * NT) * 56;
    const float* mg = mask + (size_t)w * NT * NT;
    for (int i = threadIdx.x; i < NT * 56; i += 256) {
        int r = i / 56, c = i - r * 56;
        float v = -1e30f;
        if (c < NT) {
            int ri = r / 7, rc = r - ri * 7;
            int cj = c / 7, cc = c - cj * 7;
            int rel = (ri - cj + 6) * 13 + (rc - cc + 6);
            v = __ldg(btab + rel * 8 + h) + __ldg(mg + r * NT + c);
        }
        dst[i] = v;
    }
}

// ===========================================================================
// fp16 GEMM (exact R8/R15 config — empirically best): 128x128 CTA tile,
// 128 thr, 64x64 warp tiles, 3-stage cp.async ring, ldmatrix + HMMA.16816.
// ===========================================================================
#define GSTR    72
#define GTILE_H (128 * GSTR)
#define STAGE_H (2 * GTILE_H)
#define GSMEMH  (3 * STAGE_H * 2)

__device__ __forceinline__ void stageH(__half* st, const __half* Ag, const __half* Bg,
                                       int ch, int tid) {
    #pragma unroll
    for (int t = 0; t < 16; ++t) {
        int idx = tid + t * 128;
        int tensor = idx >> 10;
        int r  = (idx >> 3) & 127;
        int c8 = idx & 7;
        const __half* src = (tensor ? Bg : Ag) + (size_t)r * 256 + ch * 64 + c8 * 8;
        cpa16(st + tensor * GTILE_H + r * GSTR + c8 * 8, src);
    }
    asm volatile("cp.async.commit_group;" ::: "memory");
}

template<bool QKVEPI, int NC>
__global__ __launch_bounds__(128, 2)
void gemmH(const __half* __restrict__ A, const __half* __restrict__ Bw,
           const float* __restrict__ bias, void* __restrict__ Cout)
{
    extern __shared__ __half smh[];
    const int tid  = threadIdx.x;
    const int lane = tid & 31;
    const int wid  = tid >> 5;
    const int tr = lane >> 2, tc = lane & 3;
    const int nt = blockIdx.x, mt = blockIdx.y;
    const int mw = wid & 1;
    const int nw = wid >> 1;

    const __half* Ag = A  + (size_t)(mt * 128) * 256;
    const __half* Bg = Bw + (size_t)(nt * 128) * 256;

    const int g8   = lane >> 3;
    const int arow = (lane & 7) + ((g8 & 1) << 3);
    const int acol = (g8 >> 1) << 3;
    const int brow = (lane & 7) + ((g8 >> 1) << 3);
    const int bcol = (g8 & 1) << 3;

    const uint32_t sb = (uint32_t)__cvta_generic_to_shared(smh);

    float acc[4][8][4];
    #pragma unroll
    for (int mi = 0; mi < 4; ++mi)
        #pragma unroll
        for (int ni = 0; ni < 8; ++ni)
            { acc[mi][ni][0]=acc[mi][ni][1]=acc[mi][ni][2]=acc[mi][ni][3]=0.f; }

    stageH(smh,           Ag, Bg, 0, tid);
    stageH(smh + STAGE_H, Ag, Bg, 1, tid);

    #pragma unroll
    for (int ch = 0; ch < 4; ++ch) {
        const int buf = ch % 3;
        if (ch < 3) asm volatile("cp.async.wait_group 1;" ::: "memory");
        else        asm volatile("cp.async.wait_group 0;" ::: "memory");
        __syncthreads();
        if (ch < 2)
            stageH(smh + ((ch + 2) % 3) * STAGE_H, Ag, Bg, ch + 2, tid);

        const uint32_t Ab = sb + (uint32_t)(buf * STAGE_H) * 2;
        const uint32_t Bb = Ab + GTILE_H * 2;
        #pragma unroll
        for (int kk = 0; kk < 4; ++kk) {
            uint32_t a[4][4];
            #pragma unroll
            for (int mi = 0; mi < 4; ++mi)
                ldsm4(a[mi][0], a[mi][1], a[mi][2], a[mi][3],
                      Ab + (uint32_t)((mw * 64 + mi * 16 + arow) * GSTR + kk * 16 + acol) * 2);
            uint32_t bf[8][2];
            #pragma unroll
            for (int p = 0; p < 4; ++p) {
                uint32_t r0, r1, r2, r3;
                ldsm4(r0, r1, r2, r3,
                      Bb + (uint32_t)((nw * 64 + p * 16 + brow) * GSTR + kk * 16 + bcol) * 2);
                bf[2 * p][0] = r0; bf[2 * p][1] = r1;
                bf[2 * p + 1][0] = r2; bf[2 * p + 1][1] = r3;
            }
            #pragma unroll
            for (int mi = 0; mi < 4; ++mi)
                #pragma unroll
                for (int ni = 0; ni < 8; ++ni)
                    mma16(acc[mi][ni], a[mi][0], a[mi][1], a[mi][2], a[mi][3],
                          bf[ni][0], bf[ni][1]);
        }
    }

    const float sc = (QKVEPI && nt < 2) ? QSCALE : 1.0f;
    #pragma unroll
    for (int ni = 0; ni < 8; ++ni) {
        int col = nt * 128 + nw * 64 + ni * 8 + tc * 2;
        float b0 = __ldg(bias + col), b1 = __ldg(bias + col + 1);
        #pragma unroll
        for (int mi = 0; mi < 4; ++mi) {
            int row = mt * 128 + mw * 64 + mi * 16 + tr;
            float v00 = acc[mi][ni][0] + b0, v01 = acc[mi][ni][1] + b1;
            float v10 = acc[mi][ni][2] + b0, v11 = acc[mi][ni][3] + b1;
            if (QKVEPI) {
                v00 *= sc; v01 *= sc; v10 *= sc; v11 *= sc;
                __half* Ch = (__half*)Cout;
                *(__half2*)(Ch + (size_t)row * NC + col)       = __floats2half2_rn(v00, v01);
                *(__half2*)(Ch + (size_t)(row + 8) * NC + col) = __floats2half2_rn(v10, v11);
            } else {
                float* Cf = (float*)Cout;
                *(float2*)(Cf + (size_t)row * NC + col)       = make_float2(v00, v01);
                *(float2*)(Cf + (size_t)(row + 8) * NC + col) = make_float2(v10, v11);
            }
        }
    }
}

// ===========================================================================
// attn2: CTA = (head, window-pair), 128 threads. Both windows' qkv staged as
// two cp.async groups up front; window 1's load hides behind window 0's
// compute. Per-window math identical to R8/R15 attnH.
// ===========================================================================
#define WBUF  7680                 // halves per window buffer (3 x 64 x 40)
#define AQS2  0                    // q offset within buffer
#define AKS2  2560                 // k
#define AVS2  5120                 // v
#define APS2  (2 * WBUF)           // P: [64][72], shared across windows
#define ATT2_H (APS2 + 64 * 72)    // 19968 halves = 39936 B

__global__ __launch_bounds__(128, 5)
void attn2(const __half* __restrict__ qkv, __half* __restrict__ O, int nW)
{
    __shared__ __half sh[ATT2_H];
    const int tid  = threadIdx.x;
    const int lane = tid & 31;
    const int wid  = tid >> 5;
    const int h  = blockIdx.x;
    const int b0 = blockIdx.y * 2;
    const int tr = lane >> 2, tc = lane & 3;
    const uint32_t sb = (uint32_t)__cvta_generic_to_shared(sh);

    // zero K,V pad rows 49..63 for BOTH buffers (600 halves per region)
    #pragma unroll
    for (int wi = 0; wi < 2; ++wi) {
        uint32_t* zk = (uint32_t*)(sh + wi * WBUF + AKS2 + NT * 40);
        uint32_t* zv = (uint32_t*)(sh + wi * WBUF + AVS2 + NT * 40);
        for (int i = tid; i < 300; i += 128) { zk[i] = 0u; zv[i] = 0u; }
    }
    // stage both windows' q/k/v head slices (one commit group per window)
    #pragma unroll
    for (int wi = 0; wi < 2; ++wi) {
        const __half* base = qkv + (size_t)(b0 + wi) * NT * 768 + h * 32;
        __half* dst = sh + wi * WBUF;
        for (int i = tid; i < NT * 4; i += 128) {
            int r = i >> 2, c = (i & 3) * 8;
            const __half* g = base + (size_t)r * 768 + c;
            cpa16(dst + AQS2 + r * 40 + c, g);
            cpa16(dst + AKS2 + r * 40 + c, g + 256);
            cpa16(dst + AVS2 + r * 40 + c, g + 512);
        }
        asm volatile("cp.async.commit_group;" ::: "memory");
    }

    const int mrow = wid * 16;
    const int g8   = lane >> 3;
    const int arow = (lane & 7) + ((g8 & 1) << 3);
    const int acol = (g8 >> 1) << 3;
    const int brow = (lane & 7) + ((g8 >> 1) << 3);
    const int bcol = (g8 & 1) << 3;

    #pragma unroll
    for (int wi = 0; wi < 2; ++wi) {
        if (wi == 0) asm volatile("cp.async.wait_group 1;" ::: "memory");
        else         asm volatile("cp.async.wait_group 0;" ::: "memory");
        __syncthreads();

        const int b = b0 + wi;
        const int w = b % nW;
        const uint32_t bufb = sb + (uint32_t)(wi * WBUF) * 2;

        // ---- S = q @ k^T (q pre-scaled; K=32 -> 2 k16 steps; 7 n-tiles) ----
        float sacc[7][4];
        #pragma unroll
        for (int t = 0; t < 7; ++t) { sacc[t][0]=sacc[t][1]=sacc[t][2]=sacc[t][3]=0.f; }
        {
            uint32_t qa[2][4];
            #pragma unroll
            for (int kk = 0; kk < 2; ++kk)
                ldsm4(qa[kk][0], qa[kk][1], qa[kk][2], qa[kk][3],
                      bufb + (uint32_t)((AQS2 + (mrow + arow) * 40 + kk * 16 + acol)) * 2);
            #pragma unroll
            for (int kk = 0; kk < 2; ++kk) {
                #pragma unroll
                for (int p = 0; p < 4; ++p) {
                    uint32_t r0, r1, r2, r3;
                    ldsm4(r0, r1, r2, r3,
                          bufb + (uint32_t)((AKS2 + (p * 16 + brow) * 40 + kk * 16 + bcol)) * 2);
                    mma16(sacc[2 * p], qa[kk][0], qa[kk][1], qa[kk][2], qa[kk][3], r0, r1);
                    if (p < 3)
                        mma16(sacc[2 * p + 1], qa[kk][0], qa[kk][1], qa[kk][2], qa[kk][3], r2, r3);
                }
            }
        }

        // ---- register softmax + P (half) smem write; zero pad cols 56..63 ----
        {
            const float* bmb = g_BM + ((size_t)(w * NH + h) * NT) * 56;
            #pragma unroll
            for (int g2 = 0; g2 < 2; ++g2) {
                int r  = mrow + tr + 8 * g2;
                int rb = (r < NT) ? r : NT - 1;
                const float* bmr = bmb + (size_t)rb * 56 + tc * 2;
                float v[7][2];
                float m = -3.4e38f;
                #pragma unroll
                for (int nt = 0; nt < 7; ++nt) {
                    float2 bm2 = *(const float2*)(bmr + nt * 8);
                    v[nt][0] = sacc[nt][2 * g2]     + bm2.x;
                    v[nt][1] = sacc[nt][2 * g2 + 1] + bm2.y;
                    m = fmaxf(m, fmaxf(v[nt][0], v[nt][1]));
                }
                m = fmaxf(m, __shfl_xor_sync(0xffffffffu, m, 1));
                m = fmaxf(m, __shfl_xor_sync(0xffffffffu, m, 2));
                float s = 0.f;
                #pragma unroll
                for (int nt = 0; nt < 7; ++nt) {
                    v[nt][0] = __expf(v[nt][0] - m);
                    v[nt][1] = __expf(v[nt][1] - m);
                    s += v[nt][0] + v[nt][1];
                }
                s += __shfl_xor_sync(0xffffffffu, s, 1);
                s += __shfl_xor_sync(0xffffffffu, s, 2);
                float inv = 1.0f / s;
                __half* pr = sh + APS2 + r * 72 + tc * 2;
                #pragma unroll
                for (int nt = 0; nt < 7; ++nt)
                    *(__half2*)(pr + nt * 8) = __floats2half2_rn(v[nt][0] * inv, v[nt][1] * inv);
                *(__half2*)(pr + 56) = __float2half2_rn(0.f);
            }
        }
        __syncwarp();   // this warp's PV reads only its own P rows

        // ---- O = P @ v (K=64 padded -> 4 k16 steps; V via trans ldmatrix) ----
        {
            float oacc[4][4];
            #pragma unroll
            for (int t = 0; t < 4; ++t) { oacc[t][0]=oacc[t][1]=oacc[t][2]=oacc[t][3]=0.f; }
            #pragma unroll
            for (int kk = 0; kk < 4; ++kk) {
                uint32_t pa0, pa1, pa2, pa3;
                ldsm4(pa0, pa1, pa2, pa3,
                      sb + (uint32_t)((APS2 + (mrow + arow) * 72 + kk * 16 + acol)) * 2);
                #pragma unroll
                for (int q = 0; q < 2; ++q) {
                    uint32_t r0, r1, r2, r3;
                    ldsm4t(r0, r1, r2, r3,
                           bufb + (uint32_t)((AVS2 + (kk * 16 + (lane & 7) + ((g8 & 1) << 3)) * 40
                                              + q * 16 + ((g8 >> 1) << 3))) * 2);
                    mma16(oacc[2 * q],     pa0, pa1, pa2, pa3, r0, r1);
                    mma16(oacc[2 * q + 1], pa0, pa1, pa2, pa3, r2, r3);
                }
            }
            __half* og = O + (size_t)b * NT * DIMC + h * HD;
            #pragma unroll
            for (int nt = 0; nt < 4; ++nt) {
                int c = nt * 8 + tc * 2;
                int r = mrow + tr;
                if (r < NT)
                    *(__half2*)(og + (size_t)r * DIMC + c) =
                        __floats2half2_rn(oacc[nt][0], oacc[nt][1]);
                if (r + 8 < NT)
                    *(__half2*)(og + (size_t)(r + 8) * DIMC + c) =
                        __floats2half2_rn(oacc[nt][2], oacc[nt][3]);
            }
        }
        __syncwarp();   // P buffer reused by this warp next window
    }
}

// ===========================================================================
extern "C" void kernel_launch(void* const* d_in, const int* in_sizes, int n_in,
                              void* d_out, int out_size)
{
    const float* x      = (const float*)d_in[0];
    const float* mask   = (const float*)d_in[1];
    const float* qkv_w  = (const float*)d_in[2];
    const float* qkv_b  = (const float*)d_in[3];
    const float* proj_w = (const float*)d_in[4];
    const float* proj_b = (const float*)d_in[5];
    const float* btab   = (const float*)d_in[6];
    float* out = (float*)d_out;

    const int B_ = in_sizes[0] / (NT * DIMC);   // 4096
    const int nW = in_sizes[1] / (NT * NT);     // 64
    const int M  = B_ * NT;                     // 200704

    __half *xh, *qkvh, *oh, *wq, *wp;
    cudaGetSymbolAddress((void**)&xh,   g_Xh);
    cudaGetSymbolAddress((void**)&qkvh, g_QKV);
    cudaGetSymbolAddress((void**)&oh,   g_Oh);
    cudaGetSymbolAddress((void**)&wq,   g_Wq);
    cudaGetSymbolAddress((void**)&wp,   g_Wp);

    static int smem_set = 0;
    if (!smem_set) {
        cudaFuncSetAttribute(gemmH<true, 768>,  cudaFuncAttributeMaxDynamicSharedMemorySize, GSMEMH);
        cudaFuncSetAttribute(gemmH<false, 256>, cudaFuncAttributeMaxDynamicSharedMemorySize, GSMEMH);
        smem_set = 1;
    }

    // 1) operand prep: fp32 -> fp16 + combined bias/mask table
    convX<<<(M * DIMC) / 1024, 256>>>((const float4*)x, (__half2*)xh);
    convW<<<256, 256>>>((const float4*)qkv_w, (const float4*)proj_w,
                        (__half2*)wq, (__half2*)wp);
    prepBM<<<dim3(NH, nW), 256>>>(mask, btab);

    // 2) QKV = Xh @ Wq^T + b  (q pre-scaled, fp16 out)
    gemmH<true, 768><<<dim3(6, M / 128), 128, GSMEMH>>>(xh, wq, qkv_b, qkvh);

    // 3) windowed attention: CTA = (head, window-pair), pipelined staging
    attn2<<<dim3(NH, B_ / 2), 128>>>(qkvh, oh, nW);

    // 4) out = O @ Wp^T + b (fp32 out)
    gemmH<false, 256><<<dim3(2, M / 128), 128, GSMEMH>>>(oh, wp, proj_b, out);
}

// round 17
// speedup vs baseline: 1.0482x; 1.0482x over previous
#include <cuda_runtime.h>
#include <cuda_fp16.h>
#include <cstdint>

#define NT     49
#define DIMC   256
#define NH     8
#define HD     32
#define QSCALE 0.17677669529663687f   // 32^-0.5
#define MAXB   4096
#define MAXW   64

// ------------------------- global scratch ---------------------------------
__device__ __half g_Xh [(size_t)MAXB * NT * DIMC];        // fp16 x
__device__ __half g_QKV[(size_t)MAXB * NT * 3 * DIMC];    // fp16 qkv activations
__device__ __half g_Oh [(size_t)MAXB * NT * DIMC];        // fp16 attention out
__device__ __half g_Wq [3 * DIMC * DIMC];                 // fp16 qkv_w
__device__ __half g_Wp [DIMC * DIMC];                     // fp16 proj_w
__device__ float  g_BM [(size_t)MAXW * NH * NT * 56];     // bias+mask, pad=-1e30

// ---------------------------------------------------------------------------
__device__ __forceinline__ void cpa16(void* smem_dst, const void* gsrc) {
    unsigned d = (unsigned)__cvta_generic_to_shared(smem_dst);
    asm volatile("cp.async.cg.shared.global [%0], [%1], 16;" :: "r"(d), "l"(gsrc));
}

__device__ __forceinline__ void mma16(float* c,
                                      uint32_t a0, uint32_t a1, uint32_t a2, uint32_t a3,
                                      uint32_t b0, uint32_t b1) {
    asm volatile(
        "mma.sync.aligned.m16n8k16.row.col.f32.f16.f16.f32 "
        "{%0,%1,%2,%3}, {%4,%5,%6,%7}, {%8,%9}, {%0,%1,%2,%3};"
        : "+f"(c[0]), "+f"(c[1]), "+f"(c[2]), "+f"(c[3])
        : "r"(a0), "r"(a1), "r"(a2), "r"(a3), "r"(b0), "r"(b1));
}

__device__ __forceinline__ void ldsm4(uint32_t& r0, uint32_t& r1,
                                      uint32_t& r2, uint32_t& r3, uint32_t addr) {
    asm volatile("ldmatrix.sync.aligned.m8n8.x4.shared.b16 {%0,%1,%2,%3}, [%4];"
                 : "=r"(r0), "=r"(r1), "=r"(r2), "=r"(r3) : "r"(addr));
}

__device__ __forceinline__ void ldsm4t(uint32_t& r0, uint32_t& r1,
                                       uint32_t& r2, uint32_t& r3, uint32_t addr) {
    asm volatile("ldmatrix.sync.aligned.m8n8.x4.trans.shared.b16 {%0,%1,%2,%3}, [%4];"
                 : "=r"(r0), "=r"(r1), "=r"(r2), "=r"(r3) : "r"(addr));
}

// ===========================================================================
// prep kernels: fp32 -> fp16 conversion + bias/mask table
// ===========================================================================
__global__ void convX(const float4* __restrict__ src, __half2* __restrict__ dst) {
    size_t i = (size_t)blockIdx.x * 256 + threadIdx.x;
    float4 v = src[i];
    dst[2 * i]     = __floats2half2_rn(v.x, v.y);
    dst[2 * i + 1] = __floats2half2_rn(v.z, v.w);
}

__global__ void convW(const float4* __restrict__ qw, const float4* __restrict__ pw,
                      __half2* __restrict__ qwt, __half2* __restrict__ pwt) {
    int i = blockIdx.x * 256 + threadIdx.x;          // 65536 threads
    if (i < 49152) {
        float4 v = qw[i];
        qwt[2 * i]     = __floats2half2_rn(v.x, v.y);
        qwt[2 * i + 1] = __floats2half2_rn(v.z, v.w);
    } else {
        int j = i - 49152;
        float4 v = pw[j];
        pwt[2 * j]     = __floats2half2_rn(v.x, v.y);
        pwt[2 * j + 1] = __floats2half2_rn(v.z, v.w);
    }
}

__global__ void prepBM(const float* __restrict__ mask,
                       const float* __restrict__ btab) {
    const int h = blockIdx.x, w = blockIdx.y;
    float* dst = g_BM + ((size_t)(w * NH + h) * NT) * 56;
    const float* mg = mask + (size_t)w * NT * NT;
    for (int i = threadIdx.x; i < NT * 56; i += 256) {
        int r = i / 56, c = i - r * 56;
        float v = -1e30f;
        if (c < NT) {
            int ri = r / 7, rc = r - ri * 7;
            int cj = c / 7, cc = c - cj * 7;
            int rel = (ri - cj + 6) * 13 + (rc - cc + 6);
            v = __ldg(btab + rel * 8 + h) + __ldg(mg + r * NT + c);
        }
        dst[i] = v;
    }
}

// ===========================================================================
// fp16 GEMM: 128x128 CTA tile, 128 thr, 64x64 warp tiles, 3-stage cp.async
// ring, ldmatrix + HMMA.16816.  Epilogue round-trips the C tile through the
// stage smem so all global stores are coalesced 16B uint4.
// ===========================================================================
#define GSTR    72
#define GTILE_H (128 * GSTR)
#define STAGE_H (2 * GTILE_H)
#define GSMEMH  (3 * STAGE_H * 2)   // 110592 B
#define EPI_HSTR 136                // fp16 epilogue smem stride (halves)
#define EPI_FSTR 132                // fp32 epilogue smem stride (floats)

__device__ __forceinline__ void stageH(__half* st, const __half* Ag, const __half* Bg,
                                       int ch, int tid) {
    #pragma unroll
    for (int t = 0; t < 16; ++t) {
        int idx = tid + t * 128;
        int tensor = idx >> 10;
        int r  = (idx >> 3) & 127;
        int c8 = idx & 7;
        const __half* src = (tensor ? Bg : Ag) + (size_t)r * 256 + ch * 64 + c8 * 8;
        cpa16(st + tensor * GTILE_H + r * GSTR + c8 * 8, src);
    }
    asm volatile("cp.async.commit_group;" ::: "memory");
}

template<bool QKVEPI, int NC>
__global__ __launch_bounds__(128, 2)
void gemmH(const __half* __restrict__ A, const __half* __restrict__ Bw,
           const float* __restrict__ bias, void* __restrict__ Cout)
{
    extern __shared__ __half smh[];
    const int tid  = threadIdx.x;
    const int lane = tid & 31;
    const int wid  = tid >> 5;
    const int tr = lane >> 2, tc = lane & 3;
    const int nt = blockIdx.x, mt = blockIdx.y;
    const int mw = wid & 1;
    const int nw = wid >> 1;

    const __half* Ag = A  + (size_t)(mt * 128) * 256;
    const __half* Bg = Bw + (size_t)(nt * 128) * 256;

    const int g8   = lane >> 3;
    const int arow = (lane & 7) + ((g8 & 1) << 3);
    const int acol = (g8 >> 1) << 3;
    const int brow = (lane & 7) + ((g8 >> 1) << 3);
    const int bcol = (g8 & 1) << 3;

    const uint32_t sb = (uint32_t)__cvta_generic_to_shared(smh);

    float acc[4][8][4];
    #pragma unroll
    for (int mi = 0; mi < 4; ++mi)
        #pragma unroll
        for (int ni = 0; ni < 8; ++ni)
            { acc[mi][ni][0]=acc[mi][ni][1]=acc[mi][ni][2]=acc[mi][ni][3]=0.f; }

    stageH(smh,           Ag, Bg, 0, tid);
    stageH(smh + STAGE_H, Ag, Bg, 1, tid);

    #pragma unroll
    for (int ch = 0; ch < 4; ++ch) {
        const int buf = ch % 3;
        if (ch < 3) asm volatile("cp.async.wait_group 1;" ::: "memory");
        else        asm volatile("cp.async.wait_group 0;" ::: "memory");
        __syncthreads();
        if (ch < 2)
            stageH(smh + ((ch + 2) % 3) * STAGE_H, Ag, Bg, ch + 2, tid);

        const uint32_t Ab = sb + (uint32_t)(buf * STAGE_H) * 2;
        const uint32_t Bb = Ab + GTILE_H * 2;
        #pragma unroll
        for (int kk = 0; kk < 4; ++kk) {
            uint32_t a[4][4];
            #pragma unroll
            for (int mi = 0; mi < 4; ++mi)
                ldsm4(a[mi][0], a[mi][1], a[mi][2], a[mi][3],
                      Ab + (uint32_t)((mw * 64 + mi * 16 + arow) * GSTR + kk * 16 + acol) * 2);
            uint32_t bf[8][2];
            #pragma unroll
            for (int p = 0; p < 4; ++p) {
                uint32_t r0, r1, r2, r3;
                ldsm4(r0, r1, r2, r3,
                      Bb + (uint32_t)((nw * 64 + p * 16 + brow) * GSTR + kk * 16 + bcol) * 2);
                bf[2 * p][0] = r0; bf[2 * p][1] = r1;
                bf[2 * p + 1][0] = r2; bf[2 * p + 1][1] = r3;
            }
            #pragma unroll
            for (int mi = 0; mi < 4; ++mi)
                #pragma unroll
                for (int ni = 0; ni < 8; ++ni)
                    mma16(acc[mi][ni], a[mi][0], a[mi][1], a[mi][2], a[mi][3],
                          bf[ni][0], bf[ni][1]);
        }
    }

    // ---- epilogue: bias add in regs -> smem C tile -> coalesced 16B STG ----
    __syncthreads();   // all warps done reading stage buffers
    const float sc = (QKVEPI && nt < 2) ? QSCALE : 1.0f;

    if (QKVEPI) {
        __half* smc = smh;   // 128 x EPI_HSTR halves = 34816 B
        #pragma unroll
        for (int ni = 0; ni < 8; ++ni) {
            int col = nw * 64 + ni * 8 + tc * 2;
            float b0 = __ldg(bias + nt * 128 + col), b1 = __ldg(bias + nt * 128 + col + 1);
            #pragma unroll
            for (int mi = 0; mi < 4; ++mi) {
                int row = mw * 64 + mi * 16 + tr;
                *(__half2*)(smc + row * EPI_HSTR + col) =
                    __floats2half2_rn((acc[mi][ni][0] + b0) * sc, (acc[mi][ni][1] + b1) * sc);
                *(__half2*)(smc + (row + 8) * EPI_HSTR + col) =
                    __floats2half2_rn((acc[mi][ni][2] + b0) * sc, (acc[mi][ni][3] + b1) * sc);
            }
        }
        __syncthreads();
        __half* Ch = (__half*)Cout + (size_t)(mt * 128) * NC + nt * 128;
        #pragma unroll
        for (int t = 0; t < 16; ++t) {
            int i = tid + t * 128;          // 0..2047
            int r = i >> 4, c8 = i & 15;
            *(uint4*)(Ch + (size_t)r * NC + c8 * 8) =
                *(const uint4*)(smc + r * EPI_HSTR + c8 * 8);
        }
    } else {
        float* smc = (float*)smh;  // 128 x EPI_FSTR floats = 67584 B
        #pragma unroll
        for (int ni = 0; ni < 8; ++ni) {
            int col = nw * 64 + ni * 8 + tc * 2;
            float b0 = __ldg(bias + nt * 128 + col), b1 = __ldg(bias + nt * 128 + col + 1);
            #pragma unroll
            for (int mi = 0; mi < 4; ++mi) {
                int row = mw * 64 + mi * 16 + tr;
                *(float2*)(smc + row * EPI_FSTR + col) =
                    make_float2(acc[mi][ni][0] + b0, acc[mi][ni][1] + b1);
                *(float2*)(smc + (row + 8) * EPI_FSTR + col) =
                    make_float2(acc[mi][ni][2] + b0, acc[mi][ni][3] + b1);
            }
        }
        __syncthreads();
        float* Cf = (float*)Cout + (size_t)(mt * 128) * NC + nt * 128;
        #pragma unroll
        for (int t = 0; t < 32; ++t) {
            int i = tid + t * 128;          // 0..4095
            int r = i >> 5, c4 = i & 31;
            *(uint4*)(Cf + (size_t)r * NC + c4 * 4) =
                *(const uint4*)(smc + r * EPI_FSTR + c4 * 4);
        }
    }
}

// ===========================================================================
// fp16 attention (exact R15 config): CTA = (head, window), 128 threads,
// ldmatrix + HMMA, occupancy cap 7.
// ===========================================================================
#define AQS 0
#define AKS (64 * 40)
#define AVS (2 * 64 * 40)
#define APS (3 * 64 * 40)
#define ATT_H (APS + 64 * 72)

__global__ __launch_bounds__(128, 7)
void attnH(const __half* __restrict__ qkv, __half* __restrict__ O, int nW)
{
    __shared__ __half sh[ATT_H];
    const int tid  = threadIdx.x;
    const int lane = tid & 31;
    const int wid  = tid >> 5;
    const int h = blockIdx.x;
    const int b = blockIdx.y;
    const int w = b % nW;
    const int tr = lane >> 2, tc = lane & 3;
    const uint32_t sb = (uint32_t)__cvta_generic_to_shared(sh);

    {
        uint32_t* zk = (uint32_t*)(sh + AKS + NT * 40);
        uint32_t* zv = (uint32_t*)(sh + AVS + NT * 40);
        for (int i = tid; i < 300; i += 128) { zk[i] = 0u; zv[i] = 0u; }
    }
    {
        const __half* base = qkv + (size_t)b * NT * 768 + h * 32;
        for (int i = tid; i < NT * 4; i += 128) {
            int r = i >> 2, c = (i & 3) * 8;
            const __half* g = base + (size_t)r * 768 + c;
            cpa16(sh + AQS + r * 40 + c, g);
            cpa16(sh + AKS + r * 40 + c, g + 256);
            cpa16(sh + AVS + r * 40 + c, g + 512);
        }
        asm volatile("cp.async.commit_group;" ::: "memory");
        asm volatile("cp.async.wait_group 0;" ::: "memory");
    }
    __syncthreads();

    const int mrow = wid * 16;
    const int g8   = lane >> 3;
    const int arow = (lane & 7) + ((g8 & 1) << 3);
    const int acol = (g8 >> 1) << 3;
    const int brow = (lane & 7) + ((g8 >> 1) << 3);
    const int bcol = (g8 & 1) << 3;

    float sacc[7][4];
    #pragma unroll
    for (int t = 0; t < 7; ++t) { sacc[t][0]=sacc[t][1]=sacc[t][2]=sacc[t][3]=0.f; }
    {
        uint32_t qa[2][4];
        #pragma unroll
        for (int kk = 0; kk < 2; ++kk)
            ldsm4(qa[kk][0], qa[kk][1], qa[kk][2], qa[kk][3],
                  sb + (uint32_t)((AQS + (mrow + arow) * 40 + kk * 16 + acol)) * 2);
        #pragma unroll
        for (int kk = 0; kk < 2; ++kk) {
            #pragma unroll
            for (int p = 0; p < 4; ++p) {
                uint32_t r0, r1, r2, r3;
                ldsm4(r0, r1, r2, r3,
                      sb + (uint32_t)((AKS + (p * 16 + brow) * 40 + kk * 16 + bcol)) * 2);
                mma16(sacc[2 * p], qa[kk][0], qa[kk][1], qa[kk][2], qa[kk][3], r0, r1);
                if (p < 3)
                    mma16(sacc[2 * p + 1], qa[kk][0], qa[kk][1], qa[kk][2], qa[kk][3], r2, r3);
            }
        }
    }

    {
        const float* bmb = g_BM + ((size_t)(w * NH + h) * NT) * 56;
        #pragma unroll
        for (int g2 = 0; g2 < 2; ++g2) {
            int r  = mrow + tr + 8 * g2;
            int rb = (r < NT) ? r : NT - 1;
            const float* bmr = bmb + (size_t)rb * 56 + tc * 2;
            float v[7][2];
            float m = -3.4e38f;
            #pragma unroll
            for (int nt = 0; nt < 7; ++nt) {
                float2 bm2 = *(const float2*)(bmr + nt * 8);
                v[nt][0] = sacc[nt][2 * g2]     + bm2.x;
                v[nt][1] = sacc[nt][2 * g2 + 1] + bm2.y;
                m = fmaxf(m, fmaxf(v[nt][0], v[nt][1]));
            }
            m = fmaxf(m, __shfl_xor_sync(0xffffffffu, m, 1));
            m = fmaxf(m, __shfl_xor_sync(0xffffffffu, m, 2));
            float s = 0.f;
            #pragma unroll
            for (int nt = 0; nt < 7; ++nt) {
                v[nt][0] = __expf(v[nt][0] - m);
                v[nt][1] = __expf(v[nt][1] - m);
                s += v[nt][0] + v[nt][1];
            }
            s += __shfl_xor_sync(0xffffffffu, s, 1);
            s += __shfl_xor_sync(0xffffffffu, s, 2);
            float inv = 1.0f / s;
            __half* pr = sh + APS + r * 72 + tc * 2;
            #pragma unroll
            for (int nt = 0; nt < 7; ++nt)
                *(__half2*)(pr + nt * 8) = __floats2half2_rn(v[nt][0] * inv, v[nt][1] * inv);
            *(__half2*)(pr + 56) = __float2half2_rn(0.f);
        }
    }
    __syncwarp();

    {
        float oacc[4][4];
        #pragma unroll
        for (int t = 0; t < 4; ++t) { oacc[t][0]=oacc[t][1]=oacc[t][2]=oacc[t][3]=0.f; }
        #pragma unroll
        for (int kk = 0; kk < 4; ++kk) {
            uint32_t pa0, pa1, pa2, pa3;
            ldsm4(pa0, pa1, pa2, pa3,
                  sb + (uint32_t)((APS + (mrow + arow) * 72 + kk * 16 + acol)) * 2);
            #pragma unroll
            for (int q = 0; q < 2; ++q) {
                uint32_t r0, r1, r2, r3;
                ldsm4t(r0, r1, r2, r3,
                       sb + (uint32_t)((AVS + (kk * 16 + (lane & 7) + ((g8 & 1) << 3)) * 40
                                        + q * 16 + ((g8 >> 1) << 3))) * 2);
                mma16(oacc[2 * q],     pa0, pa1, pa2, pa3, r0, r1);
                mma16(oacc[2 * q + 1], pa0, pa1, pa2, pa3, r2, r3);
            }
        }
        __half* og = O + (size_t)b * NT * DIMC + h * HD;
        #pragma unroll
        for (int nt = 0; nt < 4; ++nt) {
            int c = nt * 8 + tc * 2;
            int r = mrow + tr;
            if (r < NT)
                *(__half2*)(og + (size_t)r * DIMC + c) =
                    __floats2half2_rn(oacc[nt][0], oacc[nt][1]);
            if (r + 8 < NT)
                *(__half2*)(og + (size_t)(r + 8) * DIMC + c) =
                    __floats2half2_rn(oacc[nt][2], oacc[nt][3]);
        }
    }
}

// ===========================================================================
extern "C" void kernel_launch(void* const* d_in, const int* in_sizes, int n_in,
                              void* d_out, int out_size)
{
    const float* x      = (const float*)d_in[0];
    const float* mask   = (const float*)d_in[1];
    const float* qkv_w  = (const float*)d_in[2];
    const float* qkv_b  = (const float*)d_in[3];
    const float* proj_w = (const float*)d_in[4];
    const float* proj_b = (const float*)d_in[5];
    const float* btab   = (const float*)d_in[6];
    float* out = (float*)d_out;

    const int B_ = in_sizes[0] / (NT * DIMC);   // 4096
    const int nW = in_sizes[1] / (NT * NT);     // 64
    const int M  = B_ * NT;                     // 200704

    __half *xh, *qkvh, *oh, *wq, *wp;
    cudaGetSymbolAddress((void**)&xh,   g_Xh);
    cudaGetSymbolAddress((void**)&qkvh, g_QKV);
    cudaGetSymbolAddress((void**)&oh,   g_Oh);
    cudaGetSymbolAddress((void**)&wq,   g_Wq);
    cudaGetSymbolAddress((void**)&wp,   g_Wp);

    static int smem_set = 0;
    if (!smem_set) {
        cudaFuncSetAttribute(gemmH<true, 768>,  cudaFuncAttributeMaxDynamicSharedMemorySize, GSMEMH);
        cudaFuncSetAttribute(gemmH<false, 256>, cudaFuncAttributeMaxDynamicSharedMemorySize, GSMEMH);
        smem_set = 1;
    }

    // 1) operand prep: fp32 -> fp16 + combined bias/mask table
    convX<<<(M * DIMC) / 1024, 256>>>((const float4*)x, (__half2*)xh);
    convW<<<256, 256>>>((const float4*)qkv_w, (const float4*)proj_w,
                        (__half2*)wq, (__half2*)wp);
    prepBM<<<dim3(NH, nW), 256>>>(mask, btab);

    // 2) QKV = Xh @ Wq^T + b  (q pre-scaled, fp16 out)
    gemmH<true, 768><<<dim3(6, M / 128), 128, GSMEMH>>>(xh, wq, qkv_b, qkvh);

    // 3) windowed attention per (head, window)
    attnH<<<dim3(NH, B_), 128>>>(qkvh, oh, nW);

    // 4) out = O @ Wp^T + b (fp32 out)
    gemmH<false, 256><<<dim3(2, M / 128), 128, GSMEMH>>>(oh, wp, proj_b, out);
}